// round 13
// baseline (speedup 1.0000x reference)
#include <cuda_runtime.h>
#include <cuda_bf16.h>
#include <cstdint>

#define Bdim 64
#define Adim 128
#define Tdim 6
#define Ddim 256
#define Hdim 512
#define NBdim 5
#define OUTdim 401

#define ROWS (Bdim * Adim * Tdim) /* 49152 */
#define BAn (Bdim * Adim)         /* 8192  */

// ---------------- scratch (__device__ globals; allocation-free rule) -------
__device__ float g_S[ROWS * Ddim];
__device__ float g_SNEW[ROWS * Ddim];
__device__ float g_C[BAn * Ddim];
__device__ float g_CNEW[BAn * Ddim];
__device__ float g_RES[ROWS * OUTdim];
__device__ float g_SM0[Tdim * Ddim]; // iter-0 s-MLP (6 unique rows)

__device__ __nv_bfloat16 g_Hhi[ROWS * Hdim];
__device__ __nv_bfloat16 g_Hlo[ROWS * Hdim];
__device__ __nv_bfloat16 g_HChi[BAn * Hdim];
__device__ __nv_bfloat16 g_HClo[BAn * Hdim];
__device__ __nv_bfloat16 g_Shi[ROWS * Ddim];
__device__ __nv_bfloat16 g_Slo[ROWS * Ddim];
__device__ __nv_bfloat16 g_Chi[BAn * Ddim];
__device__ __nv_bfloat16 g_Clo[BAn * Ddim];

// transposed+split weights: WT[N][K] bf16 (hi and lo arrays)
#define WOFF_SW1 0
#define WOFF_SW2 327680
#define WOFF_CW1 655360
#define WOFF_CW2 983040
#define WOFF_DW1 1310720
#define WOFF_DW2 1441792
#define WTOT     1647104
__device__ __nv_bfloat16 g_WThi[WTOT];
__device__ __nv_bfloat16 g_WTlo[WTOT];

// ---------------- helpers --------------------------------------------------
__device__ __forceinline__ uint32_t smem_to_u32(const void* p) {
    uint32_t a;
    asm("{ .reg .u64 t; cvta.to.shared.u64 t, %1; cvt.u32.u64 %0, t; }"
        : "=r"(a) : "l"(p));
    return a;
}
__device__ __forceinline__ void cp16(uint32_t dst, const void* src) {
    asm volatile("cp.async.cg.shared.global [%0], [%1], 16;"
                 :: "r"(dst), "l"(src));
}
__device__ __forceinline__ void cp16z(uint32_t dst, const void* src, int zf) {
    asm volatile("cp.async.cg.shared.global [%0], [%1], 16, %2;"
                 :: "r"(dst), "l"(src), "r"(zf));
}
#define CP_COMMIT() asm volatile("cp.async.commit_group;" ::: "memory")
#define CP_WAIT1()  asm volatile("cp.async.wait_group 1;" ::: "memory")

__device__ __forceinline__ void ldm_x4(uint32_t* r, uint32_t addr) {
    asm volatile("ldmatrix.sync.aligned.m8n8.x4.shared.b16 {%0,%1,%2,%3}, [%4];"
                 : "=r"(r[0]), "=r"(r[1]), "=r"(r[2]), "=r"(r[3]) : "r"(addr));
}
__device__ __forceinline__ void mma_bf16(float* c, const uint32_t* a, const uint32_t* b) {
    asm volatile(
        "mma.sync.aligned.m16n8k16.row.col.f32.bf16.bf16.f32 "
        "{%0,%1,%2,%3},{%4,%5,%6,%7},{%8,%9},{%0,%1,%2,%3};"
        : "+f"(c[0]), "+f"(c[1]), "+f"(c[2]), "+f"(c[3])
        : "r"(a[0]), "r"(a[1]), "r"(a[2]), "r"(a[3]), "r"(b[0]), "r"(b[1]));
}
__device__ __forceinline__ void split_bf16(float v, __nv_bfloat16& hi, __nv_bfloat16& lo) {
    hi = __float2bfloat16(v);
    lo = __float2bfloat16(v - __bfloat162float(hi));
}

// ---------------------------------------------------------------------------
// HMMA GEMM: out[M,N] = A[M,K] @ WT[N,K]^T (+bias), bf16 hi/lo 3-term split.
// Tile 128x128x32, 256 thr (8 warps, 2x4), warp tile 64x32.
// 2-stage cp.async double buffer; __launch_bounds__(256,2) -> 2 CTAs/SM.
// Per-warp ntmax skips whole n-fragment groups when the CTA's n-range is
// partially OOB (decoder-2 N=401 tail): warp-uniform branches, no divergence.
// Dual-problem batching via yS (problem 1 uses MODE-0 epilogue).
// MODE 0: relu -> bf16 hi/lo; MODE 1: fp32; MODE 2: snew/s-update fused.
// ---------------------------------------------------------------------------
#define ROWB 80
#define OFF_AHI 0
#define OFF_ALO 10240
#define OFF_BHI 20480
#define OFF_BLO 30720
#define STAGE_B 40960
#define NSTAGE 2
#define GEMM_SMEM (NSTAGE * STAGE_B)

template <int MODE>
__device__ __forceinline__ void emit_elem(
    int row, int col, int N, float v, const float* __restrict__ bias,
    float* __restrict__ outF, __nv_bfloat16* __restrict__ outHi,
    __nv_bfloat16* __restrict__ outLo, int ldOut,
    const float* __restrict__ cnew, float* __restrict__ snew, float* __restrict__ sF) {
    if (col >= N) return;
    v += bias[col];
    const size_t idx = (size_t)row * ldOut + col;
    if (MODE == 0) {
        float h = fmaxf(v, 0.f);
        __nv_bfloat16 hi, lo;
        split_bf16(h, hi, lo);
        outHi[idx] = hi;
        outLo[idx] = lo;
    } else if (MODE == 1) {
        outF[idx] = v;
    } else {
        const float prod = v * cnew[(size_t)(row / Tdim) * Ddim + col];
        snew[idx] = prod;
        const float s = 0.5f * sF[idx] + 0.5f * prod;
        sF[idx] = s;
        __nv_bfloat16 hi, lo;
        split_bf16(s, hi, lo);
        outHi[idx] = hi;
        outLo[idx] = lo;
    }
}

template <int MODE>
__global__ void __launch_bounds__(256, 2) hmma_gemm(
    const __nv_bfloat16* __restrict__ A0hi, const __nv_bfloat16* __restrict__ A0lo, int ldA0,
    const __nv_bfloat16* __restrict__ B0hi, const __nv_bfloat16* __restrict__ B0lo,
    const float* __restrict__ bias0, int N, int K,
    float* __restrict__ outF, __nv_bfloat16* __restrict__ out0Hi,
    __nv_bfloat16* __restrict__ out0Lo, int ldOut0,
    const float* __restrict__ cnew, float* __restrict__ snew, float* __restrict__ sF,
    int yS,
    const __nv_bfloat16* __restrict__ A1hi, const __nv_bfloat16* __restrict__ A1lo, int ldA1,
    const __nv_bfloat16* __restrict__ B1hi, const __nv_bfloat16* __restrict__ B1lo,
    const float* __restrict__ bias1,
    __nv_bfloat16* __restrict__ out1Hi, __nv_bfloat16* __restrict__ out1Lo, int ldOut1) {
    extern __shared__ char smem[];
    const uint32_t sb = smem_to_u32(smem);
    const int tid = threadIdx.x;
    const int wid = tid >> 5;
    const int lid = tid & 31;
    const int wm = wid & 1;   // 0..1
    const int wn = wid >> 1;  // 0..3

    const bool p1 = ((int)blockIdx.y >= yS);
    const int bm = (p1 ? (int)blockIdx.y - yS : (int)blockIdx.y) * 128;
    const int bn = blockIdx.x * 128;
    const __nv_bfloat16* Ahi = p1 ? A1hi : A0hi;
    const __nv_bfloat16* Alo = p1 ? A1lo : A0lo;
    const __nv_bfloat16* Bhi = p1 ? B1hi : B0hi;
    const __nv_bfloat16* Blo = p1 ? B1lo : B0lo;
    const float* bias = p1 ? bias1 : bias0;
    const int ldA = p1 ? ldA1 : ldA0;
    const int ldOut = p1 ? ldOut1 : ldOut0;
    __nv_bfloat16* outHi = p1 ? out1Hi : out0Hi;
    __nv_bfloat16* outLo = p1 ? out1Lo : out0Lo;

    // per-warp valid n-fragment count (8 cols each); 4 = full
    int ntmax = (N - bn - wn * 32 + 7) >> 3;
    ntmax = ntmax < 0 ? 0 : (ntmax > 4 ? 4 : ntmax);
    const int pmax = (ntmax + 1) >> 1;

    float acc[4][4][4];
#pragma unroll
    for (int i = 0; i < 4; i++)
#pragma unroll
        for (int j = 0; j < 4; j++)
#pragma unroll
            for (int e = 0; e < 4; e++) acc[i][j][e] = 0.f;

    const int niters = K >> 5;

    // ---- stage loader: 8 cp.async / thread ----
    auto stage_load = [&](int stage, int k0) {
        const uint32_t st = sb + stage * STAGE_B;
        const int cid0 = tid * 2;
#pragma unroll
        for (int i = 0; i < 2; i++) {
            const int cid = cid0 + i;
            const int row = cid >> 2;
            const int c = cid & 3;
            const uint32_t soff = row * ROWB + c * 16;
            const size_t ga = (size_t)(bm + row) * ldA + k0 + c * 8;
            cp16(st + OFF_AHI + soff, Ahi + ga);
            cp16(st + OFF_ALO + soff, Alo + ga);
            const int n = bn + row;
            const int zf = (n < N) ? 16 : 0;
            const size_t gb = (size_t)(n < N ? n : 0) * K + k0 + c * 8;
            cp16z(st + OFF_BHI + soff, Bhi + gb, zf);
            cp16z(st + OFF_BLO + soff, Blo + gb, zf);
        }
    };

    stage_load(0, 0);
    CP_COMMIT();
    if (niters > 1) stage_load(1, 32);
    CP_COMMIT();

    // lane addressing for ldmatrix (loop-invariant)
    const int ar = wm * 64 + (lid & 15);
    const int br = wn * 32 + (lid & 7) + ((lid & 16) ? 8 : 0);

    for (int it = 0; it < niters; ++it) {
        CP_WAIT1();
        __syncthreads();

        const uint32_t st = sb + (it & 1) * STAGE_B;
        const uint32_t aHi = st + OFF_AHI, aLo = st + OFF_ALO;
        const uint32_t bHi = st + OFF_BHI, bLo = st + OFF_BLO;

#pragma unroll
        for (int ks = 0; ks < 2; ks++) {
            const int k0 = ks * 16;
            const int ak = k0 + ((lid >> 4) << 3);
            const int bk = k0 + ((lid & 8) ? 8 : 0);

            uint32_t bfh[4][2], bfl[4][2];
#pragma unroll
            for (int p = 0; p < 2; p++) {
                if (p < pmax) {
                    const uint32_t bo = (uint32_t)((br + p * 16) * ROWB + bk * 2);
                    uint32_t r[4];
                    ldm_x4(r, bHi + bo);
                    bfh[2 * p][0] = r[0]; bfh[2 * p][1] = r[1];
                    bfh[2 * p + 1][0] = r[2]; bfh[2 * p + 1][1] = r[3];
                    ldm_x4(r, bLo + bo);
                    bfl[2 * p][0] = r[0]; bfl[2 * p][1] = r[1];
                    bfl[2 * p + 1][0] = r[2]; bfl[2 * p + 1][1] = r[3];
                }
            }
            // A fragments loaded per-mt to cap register liveness
#pragma unroll
            for (int mt = 0; mt < 4; mt++) {
                if (ntmax > 0) {
                    const uint32_t ao = (uint32_t)((ar + mt * 16) * ROWB + ak * 2);
                    uint32_t ah[4], al[4];
                    ldm_x4(ah, aHi + ao);
                    ldm_x4(al, aLo + ao);
#pragma unroll
                    for (int nt = 0; nt < 4; nt++) {
                        if (nt < ntmax) {
                            mma_bf16(acc[mt][nt], ah, bfh[nt]);
                            mma_bf16(acc[mt][nt], ah, bfl[nt]);
                            mma_bf16(acc[mt][nt], al, bfh[nt]);
                        }
                    }
                }
            }
        }
        __syncthreads();

        // refill the buffer just consumed (stage (it+2)&1 == it&1)
        if (it + 2 < niters) stage_load(it & 1, (it + 2) * 32);
        CP_COMMIT();
    }

    // ---- epilogue: direct register -> global ----
#pragma unroll
    for (int mt = 0; mt < 4; mt++) {
        const int row0 = bm + wm * 64 + mt * 16 + (lid >> 2);
#pragma unroll
        for (int nt = 0; nt < 4; nt++) {
            if (nt >= ntmax) continue;
            const int col0 = bn + wn * 32 + nt * 8 + 2 * (lid & 3);
            if (p1) {
                emit_elem<0>(row0, col0, N, acc[mt][nt][0], bias, outF, outHi, outLo, ldOut, cnew, snew, sF);
                emit_elem<0>(row0, col0 + 1, N, acc[mt][nt][1], bias, outF, outHi, outLo, ldOut, cnew, snew, sF);
                emit_elem<0>(row0 + 8, col0, N, acc[mt][nt][2], bias, outF, outHi, outLo, ldOut, cnew, snew, sF);
                emit_elem<0>(row0 + 8, col0 + 1, N, acc[mt][nt][3], bias, outF, outHi, outLo, ldOut, cnew, snew, sF);
            } else {
                emit_elem<MODE>(row0, col0, N, acc[mt][nt][0], bias, outF, outHi, outLo, ldOut, cnew, snew, sF);
                emit_elem<MODE>(row0, col0 + 1, N, acc[mt][nt][1], bias, outF, outHi, outLo, ldOut, cnew, snew, sF);
                emit_elem<MODE>(row0 + 8, col0, N, acc[mt][nt][2], bias, outF, outHi, outLo, ldOut, cnew, snew, sF);
                emit_elem<MODE>(row0 + 8, col0 + 1, N, acc[mt][nt][3], bias, outF, outHi, outLo, ldOut, cnew, snew, sF);
            }
        }
    }
}

// ---------------------------------------------------------------------------
// iter-0 s-shortcut: S is broadcast(anchor) -> mlp2(S) has only T=6 unique rows.
// smlp0: SM[t][d] = mlp2(anchor)[t][d], exact fp32. grid=(Tdim), 256 thr.
// ---------------------------------------------------------------------------
__global__ void smlp0(const float* __restrict__ anchor,
                      const float* __restrict__ sW1, const float* __restrict__ sb1,
                      const float* __restrict__ sW2, const float* __restrict__ sb2,
                      float* __restrict__ SM) {
    __shared__ float hsm[Ddim];
    const int t = blockIdx.x;
    const int d = threadIdx.x;
    float h = sb1[d];
    for (int k = 0; k < Ddim; k++)
        h = fmaf(anchor[t * Ddim + k], sW1[(size_t)k * Ddim + d], h);
    hsm[d] = fmaxf(h, 0.f);
    __syncthreads();
    float o = sb2[d];
    for (int k = 0; k < Ddim; k++)
        o = fmaf(hsm[k], sW2[(size_t)k * Ddim + d], o);
    SM[t * Ddim + d] = o;
}

// ---------------------------------------------------------------------------
// fused iter-0 tail: per (ba,d) thread computes all T products in-register:
//   prod_t = SM[t,d]*CNEW[ba,d]; S = .5S + .5prod (+hi/lo); C = .5C + .5max_t
// Replaces iter0_update + agg_update_c (drops SNEW round-trip entirely).
// ---------------------------------------------------------------------------
__global__ void iter0_all(const float* __restrict__ SM, const float* __restrict__ CNEW,
                          float* __restrict__ S, __nv_bfloat16* __restrict__ Shi,
                          __nv_bfloat16* __restrict__ Slo, float* __restrict__ C,
                          __nv_bfloat16* __restrict__ Chi, __nv_bfloat16* __restrict__ Clo) {
    const long i = (long)blockIdx.x * blockDim.x + threadIdx.x;
    if (i >= (long)BAn * Ddim) return;
    const long ba = i >> 8;
    const int d = (int)(i & (Ddim - 1));
    const float c = CNEW[i];
    float m = -3.4e38f;
#pragma unroll
    for (int t = 0; t < Tdim; t++) {
        const float prod = SM[t * Ddim + d] * c;
        m = fmaxf(m, prod);
        const size_t idx = (size_t)(ba * Tdim + t) * Ddim + d;
        const float s = 0.5f * S[idx] + 0.5f * prod;
        S[idx] = s;
        __nv_bfloat16 hi, lo;
        split_bf16(s, hi, lo);
        Shi[idx] = hi;
        Slo[idx] = lo;
    }
    const float v = 0.5f * C[i] + 0.5f * m;
    C[i] = v;
    __nv_bfloat16 hi, lo;
    split_bf16(v, hi, lo);
    Chi[i] = hi;
    Clo[i] = lo;
}

// ---------------------------------------------------------------------------
// weight transpose + bf16 split: W[K][N] -> WT_hi/lo[N][K]
// ---------------------------------------------------------------------------
__global__ void wtrans_banked(const float* __restrict__ sW1, const float* __restrict__ sW2,
                              const float* __restrict__ cW1, const float* __restrict__ cW2,
                              __nv_bfloat16* __restrict__ Thi, __nv_bfloat16* __restrict__ Tlo) {
    __shared__ float t[32][33];
    const int z = blockIdx.z;
    const int tensor = z / NBdim, bank = z % NBdim;
    const float* src = (tensor == 0 ? sW1 : tensor == 1 ? sW2 : tensor == 2 ? cW1 : cW2) +
                       (size_t)bank * Ddim * Ddim;
    const size_t dof = (size_t)tensor * (NBdim * Ddim * Ddim) + (size_t)bank * Ddim * Ddim;
    const int k0 = blockIdx.x * 32, n0 = blockIdx.y * 32;
    const int tx = threadIdx.x, ty = threadIdx.y;
#pragma unroll
    for (int i = 0; i < 4; i++)
        t[ty + i * 8][tx] = src[(size_t)(k0 + ty + i * 8) * Ddim + n0 + tx];
    __syncthreads();
#pragma unroll
    for (int i = 0; i < 4; i++) {
        const int n = n0 + ty + i * 8, k = k0 + tx;
        __nv_bfloat16 hi, lo;
        split_bf16(t[tx][ty + i * 8], hi, lo);
        Thi[dof + (size_t)n * Ddim + k] = hi;
        Tlo[dof + (size_t)n * Ddim + k] = lo;
    }
}

__global__ void wtrans_single(const float* __restrict__ W, int K, int N,
                              __nv_bfloat16* __restrict__ Thi, __nv_bfloat16* __restrict__ Tlo) {
    __shared__ float t[32][33];
    const int k0 = blockIdx.x * 32, n0 = blockIdx.y * 32;
    const int tx = threadIdx.x, ty = threadIdx.y;
#pragma unroll
    for (int i = 0; i < 4; i++) {
        const int k = k0 + ty + i * 8;
        t[ty + i * 8][tx] = (n0 + tx < N) ? W[(size_t)k * N + n0 + tx] : 0.f;
    }
    __syncthreads();
#pragma unroll
    for (int i = 0; i < 4; i++) {
        const int n = n0 + ty + i * 8, k = k0 + tx;
        if (n < N) {
            __nv_bfloat16 hi, lo;
            split_bf16(t[tx][ty + i * 8], hi, lo);
            Thi[(size_t)n * K + k] = hi;
            Tlo[(size_t)n * K + k] = lo;
        }
    }
}

// ---------------------------------------------------------------------------
__global__ void init_kernel(const float* __restrict__ fe, const float* __restrict__ anchor,
                            float* __restrict__ S, __nv_bfloat16* __restrict__ Shi,
                            __nv_bfloat16* __restrict__ Slo, float* __restrict__ C,
                            __nv_bfloat16* __restrict__ Chi, __nv_bfloat16* __restrict__ Clo) {
    const long i = (long)blockIdx.x * blockDim.x + threadIdx.x;
    if (i < (long)ROWS * Ddim) {
        const int d = (int)(i & (Ddim - 1));
        const int t = (int)((i >> 8) % Tdim);
        const float v = anchor[t * Ddim + d];
        S[i] = v;
        __nv_bfloat16 hi, lo;
        split_bf16(v, hi, lo);
        Shi[i] = hi;
        Slo[i] = lo;
    }
    if (i < (long)BAn * Ddim) {
        const float v = fe[i];
        C[i] = v;
        __nv_bfloat16 hi, lo;
        split_bf16(v, hi, lo);
        Chi[i] = hi;
        Clo[i] = lo;
    }
}

__global__ void agg_update_c(const float* __restrict__ snew, float* __restrict__ C,
                             __nv_bfloat16* __restrict__ Chi, __nv_bfloat16* __restrict__ Clo) {
    const long i = (long)blockIdx.x * blockDim.x + threadIdx.x;
    if (i >= (long)BAn * Ddim) return;
    const long ba = i >> 8;
    const int d = (int)(i & (Ddim - 1));
    const float* p = snew + ba * Tdim * Ddim + d;
    float m = p[0];
#pragma unroll
    for (int t = 1; t < Tdim; t++) m = fmaxf(m, p[t * Ddim]);
    const float v = 0.5f * C[i] + 0.5f * m;
    C[i] = v;
    __nv_bfloat16 hi, lo;
    split_bf16(v, hi, lo);
    Chi[i] = hi;
    Clo[i] = lo;
}

__global__ void decode_out(const float* __restrict__ res, float* __restrict__ out) {
    const long i = (long)blockIdx.x * blockDim.x + threadIdx.x;
    if (i >= (long)ROWS * 80) return;
    const long row = i / 80;
    const int j = (int)(i % 80);
    const float* r = res + row * OUTdim;

    float* coords = out + ROWS;
    coords[row * 160 + 2 * j + 0] = r[2 * j + 0];
    coords[row * 160 + 2 * j + 1] = r[2 * j + 1];

    const float av = r[160 + j], bv = r[240 + j], cv = r[320 + j];
    const float ecv = expf(cv);
    const float ch = coshf(bv) * ecv;
    const float sh = sinhf(bv) * ecv;
    float* cov = out + ROWS + (long)ROWS * 160;
    const long cb = row * 320 + (long)j * 4;
    cov[cb + 0] = expf(av) * ch;
    cov[cb + 1] = sh;
    cov[cb + 2] = sh;
    cov[cb + 3] = expf(-av) * ch;

    if (j == 0) out[row] = r[400];
}

// ---------------------------------------------------------------------------
extern "C" void kernel_launch(void* const* d_in, const int* in_sizes, int n_in,
                              void* d_out, int out_size) {
    const float* fe = (const float*)d_in[0];
    const float* anchor = (const float*)d_in[1];
    const float* sW1 = (const float*)d_in[2];
    const float* sb1 = (const float*)d_in[3];
    const float* sW2 = (const float*)d_in[4];
    const float* sb2 = (const float*)d_in[5];
    const float* cW1 = (const float*)d_in[6];
    const float* cb1 = (const float*)d_in[7];
    const float* cW2 = (const float*)d_in[8];
    const float* cb2 = (const float*)d_in[9];
    const float* dW1 = (const float*)d_in[10];
    const float* db1 = (const float*)d_in[11];
    const float* dW2 = (const float*)d_in[12];
    const float* db2 = (const float*)d_in[13];
    float* out = (float*)d_out;

    float *S, *SNEW, *C, *CNEW, *RES, *SM0;
    __nv_bfloat16 *Hhi, *Hlo, *HChi, *HClo, *Shi, *Slo, *Chi, *Clo, *WThi, *WTlo;
    cudaGetSymbolAddress((void**)&S, g_S);
    cudaGetSymbolAddress((void**)&SNEW, g_SNEW);
    cudaGetSymbolAddress((void**)&C, g_C);
    cudaGetSymbolAddress((void**)&CNEW, g_CNEW);
    cudaGetSymbolAddress((void**)&RES, g_RES);
    cudaGetSymbolAddress((void**)&SM0, g_SM0);
    cudaGetSymbolAddress((void**)&Hhi, g_Hhi);
    cudaGetSymbolAddress((void**)&Hlo, g_Hlo);
    cudaGetSymbolAddress((void**)&HChi, g_HChi);
    cudaGetSymbolAddress((void**)&HClo, g_HClo);
    cudaGetSymbolAddress((void**)&Shi, g_Shi);
    cudaGetSymbolAddress((void**)&Slo, g_Slo);
    cudaGetSymbolAddress((void**)&Chi, g_Chi);
    cudaGetSymbolAddress((void**)&Clo, g_Clo);
    cudaGetSymbolAddress((void**)&WThi, g_WThi);
    cudaGetSymbolAddress((void**)&WTlo, g_WTlo);

    cudaFuncSetAttribute(hmma_gemm<0>, cudaFuncAttributeMaxDynamicSharedMemorySize, GEMM_SMEM);
    cudaFuncSetAttribute(hmma_gemm<1>, cudaFuncAttributeMaxDynamicSharedMemorySize, GEMM_SMEM);
    cudaFuncSetAttribute(hmma_gemm<2>, cudaFuncAttributeMaxDynamicSharedMemorySize, GEMM_SMEM);

    // prep (smlp0 first so the first hmma_gemm lands early in node order for ncu)
    smlp0<<<Tdim, Ddim>>>(anchor, sW1, sb1, sW2, sb2, SM0); // bank-0 weights, fp32 inputs
    wtrans_banked<<<dim3(8, 8, 4 * NBdim), dim3(32, 8)>>>(sW1, sW2, cW1, cW2, WThi, WTlo);
    wtrans_single<<<dim3(8, 16), dim3(32, 8)>>>(dW1, Ddim, Hdim, WThi + WOFF_DW1, WTlo + WOFF_DW1);
    wtrans_single<<<dim3(16, 13), dim3(32, 8)>>>(dW2, Hdim, OUTdim, WThi + WOFF_DW2, WTlo + WOFF_DW2);

    const long NS = (long)ROWS * Ddim;
    init_kernel<<<(unsigned)((NS + 255) / 256), 256>>>(fe, anchor, S, Shi, Slo, C, Chi, Clo);

    const int BIG = 1 << 30;
    const dim3 grid1(2, ROWS / 128 + BAn / 128); // batched sG1 + cG1 (iters >= 1)
    const dim3 gridC(2, BAn / 128);              // c-GEMMs
    const dim3 gridS(2, ROWS / 128);             // sG2
    const dim3 gridD1(4, ROWS / 128);            // decoder1 N=512
    const dim3 gridD2(4, ROWS / 128);            // decoder2 N=401 (tail-skipped)

    for (int i = 0; i < NBdim; i++) {
        const size_t wo = (size_t)i * Ddim * Ddim;
        const int bo = i * Ddim;
        if (i == 0) {
            // iter 0: s path collapses to 6 unique rows (S = broadcast anchor)
            hmma_gemm<0><<<gridC, 256, GEMM_SMEM>>>(
                Chi, Clo, Ddim, WThi + WOFF_CW1 + wo, WTlo + WOFF_CW1 + wo, cb1 + bo,
                Ddim, Ddim, nullptr, HChi, HClo, Hdim, nullptr, nullptr, nullptr,
                BIG, nullptr, nullptr, 0, nullptr, nullptr, nullptr, nullptr, nullptr, 0);
            hmma_gemm<1><<<gridC, 256, GEMM_SMEM>>>(
                HChi, HClo, Hdim, WThi + WOFF_CW2 + wo, WTlo + WOFF_CW2 + wo, cb2 + bo,
                Ddim, Ddim, CNEW, nullptr, nullptr, Ddim, nullptr, nullptr, nullptr,
                BIG, nullptr, nullptr, 0, nullptr, nullptr, nullptr, nullptr, nullptr, 0);
            iter0_all<<<(BAn * Ddim + 255) / 256, 256>>>(SM0, CNEW, S, Shi, Slo, C, Chi, Clo);
        } else {
            // batched: s_hidden (relu) -> Hhi/Hlo || c_hidden (relu) -> HChi/HClo
            hmma_gemm<0><<<grid1, 256, GEMM_SMEM>>>(
                Shi, Slo, Ddim, WThi + WOFF_SW1 + wo, WTlo + WOFF_SW1 + wo, sb1 + bo,
                Ddim, Ddim, nullptr, Hhi, Hlo, Hdim, nullptr, nullptr, nullptr,
                ROWS / 128,
                Chi, Clo, Ddim, WThi + WOFF_CW1 + wo, WTlo + WOFF_CW1 + wo, cb1 + bo,
                HChi, HClo, Hdim);
            hmma_gemm<1><<<gridC, 256, GEMM_SMEM>>>(
                HChi, HClo, Hdim, WThi + WOFF_CW2 + wo, WTlo + WOFF_CW2 + wo, cb2 + bo,
                Ddim, Ddim, CNEW, nullptr, nullptr, Ddim, nullptr, nullptr, nullptr,
                BIG, nullptr, nullptr, 0, nullptr, nullptr, nullptr, nullptr, nullptr, 0);
            hmma_gemm<2><<<gridS, 256, GEMM_SMEM>>>(
                Hhi, Hlo, Hdim, WThi + WOFF_SW2 + wo, WTlo + WOFF_SW2 + wo, sb2 + bo,
                Ddim, Ddim, nullptr, Shi, Slo, Ddim, CNEW, SNEW, S,
                BIG, nullptr, nullptr, 0, nullptr, nullptr, nullptr, nullptr, nullptr, 0);
            agg_update_c<<<(BAn * Ddim + 255) / 256, 256>>>(SNEW, C, Chi, Clo);
        }
    }

    // decoder
    hmma_gemm<0><<<gridD1, 256, GEMM_SMEM>>>(
        Shi, Slo, Ddim, WThi + WOFF_DW1, WTlo + WOFF_DW1, db1,
        Hdim, Ddim, nullptr, Hhi, Hlo, Hdim, nullptr, nullptr, nullptr,
        BIG, nullptr, nullptr, 0, nullptr, nullptr, nullptr, nullptr, nullptr, 0);
    hmma_gemm<1><<<gridD2, 256, GEMM_SMEM>>>(
        Hhi, Hlo, Hdim, WThi + WOFF_DW2, WTlo + WOFF_DW2, db2,
        OUTdim, Hdim, RES, nullptr, nullptr, OUTdim, nullptr, nullptr, nullptr,
        BIG, nullptr, nullptr, 0, nullptr, nullptr, nullptr, nullptr, nullptr, 0);

    decode_out<<<(unsigned)(((long)ROWS * 80 + 255) / 256), 256>>>(RES, out);
}

// round 16
// speedup vs baseline: 1.0632x; 1.0632x over previous
#include <cuda_runtime.h>
#include <cuda_bf16.h>
#include <cstdint>

#define Bdim 64
#define Adim 128
#define Tdim 6
#define Ddim 256
#define Hdim 512
#define NBdim 5
#define OUTdim 401

#define ROWS (Bdim * Adim * Tdim) /* 49152 */
#define BAn (Bdim * Adim)         /* 8192  */

// ---------------- scratch (__device__ globals; allocation-free rule) -------
__device__ float g_S[ROWS * Ddim];
__device__ float g_SNEW[ROWS * Ddim];
__device__ float g_C[BAn * Ddim];
__device__ float g_CNEW[BAn * Ddim];
__device__ float g_RES[ROWS * OUTdim];
__device__ float g_SM0[Tdim * Ddim]; // iter-0 s-MLP (6 unique rows)

__device__ __nv_bfloat16 g_Hhi[ROWS * Hdim];
__device__ __nv_bfloat16 g_Hlo[ROWS * Hdim];
__device__ __nv_bfloat16 g_HChi[BAn * Hdim];
__device__ __nv_bfloat16 g_HClo[BAn * Hdim];
__device__ __nv_bfloat16 g_Shi[ROWS * Ddim];
__device__ __nv_bfloat16 g_Slo[ROWS * Ddim];
__device__ __nv_bfloat16 g_Chi[BAn * Ddim];
__device__ __nv_bfloat16 g_Clo[BAn * Ddim];

// transposed+split weights: WT[N][K] bf16 (hi and lo arrays)
#define WOFF_SW1 0
#define WOFF_SW2 327680
#define WOFF_CW1 655360
#define WOFF_CW2 983040
#define WOFF_DW1 1310720
#define WOFF_DW2 1441792
#define WTOT     1647104
__device__ __nv_bfloat16 g_WThi[WTOT];
__device__ __nv_bfloat16 g_WTlo[WTOT];

// ---------------- helpers --------------------------------------------------
__device__ __forceinline__ uint32_t smem_to_u32(const void* p) {
    uint32_t a;
    asm("{ .reg .u64 t; cvta.to.shared.u64 t, %1; cvt.u32.u64 %0, t; }"
        : "=r"(a) : "l"(p));
    return a;
}
__device__ __forceinline__ void cp16(uint32_t dst, const void* src) {
    asm volatile("cp.async.cg.shared.global [%0], [%1], 16;"
                 :: "r"(dst), "l"(src));
}
__device__ __forceinline__ void cp16z(uint32_t dst, const void* src, int zf) {
    asm volatile("cp.async.cg.shared.global [%0], [%1], 16, %2;"
                 :: "r"(dst), "l"(src), "r"(zf));
}
#define CP_COMMIT() asm volatile("cp.async.commit_group;" ::: "memory")
#define CP_WAIT1()  asm volatile("cp.async.wait_group 1;" ::: "memory")

__device__ __forceinline__ void ldm_x4(uint32_t* r, uint32_t addr) {
    asm volatile("ldmatrix.sync.aligned.m8n8.x4.shared.b16 {%0,%1,%2,%3}, [%4];"
                 : "=r"(r[0]), "=r"(r[1]), "=r"(r[2]), "=r"(r[3]) : "r"(addr));
}
__device__ __forceinline__ void mma_bf16(float* c, const uint32_t* a, const uint32_t* b) {
    asm volatile(
        "mma.sync.aligned.m16n8k16.row.col.f32.bf16.bf16.f32 "
        "{%0,%1,%2,%3},{%4,%5,%6,%7},{%8,%9},{%0,%1,%2,%3};"
        : "+f"(c[0]), "+f"(c[1]), "+f"(c[2]), "+f"(c[3])
        : "r"(a[0]), "r"(a[1]), "r"(a[2]), "r"(a[3]), "r"(b[0]), "r"(b[1]));
}
__device__ __forceinline__ void split_bf16(float v, __nv_bfloat16& hi, __nv_bfloat16& lo) {
    hi = __float2bfloat16(v);
    lo = __float2bfloat16(v - __bfloat162float(hi));
}

// ---------------------------------------------------------------------------
// HMMA GEMM: out[M,N] = A[M,K] @ WT[N,K]^T (+bias), bf16 hi/lo 3-term split.
// Tile 128x128x32, 256 thr (8 warps, 2x4), warp tile 64x32.
// 2-stage cp.async double buffer; __launch_bounds__(256,2) -> 2 CTAs/SM.
// TAIL template flag: compile-time 0 keeps the clean R12 mainloop (no runtime
// predication); TAIL=1 (decoder-2 only) skips OOB n-fragment groups.
// Dual-problem batching via yS (problem 1 uses MODE-0 epilogue).
// MODE 0: relu -> bf16 hi/lo; MODE 1: fp32; MODE 2: snew/s-update fused.
// ---------------------------------------------------------------------------
#define ROWB 80
#define OFF_AHI 0
#define OFF_ALO 10240
#define OFF_BHI 20480
#define OFF_BLO 30720
#define STAGE_B 40960
#define NSTAGE 2
#define GEMM_SMEM (NSTAGE * STAGE_B)

template <int MODE>
__device__ __forceinline__ void emit_elem(
    int row, int col, int N, float v, const float* __restrict__ bias,
    float* __restrict__ outF, __nv_bfloat16* __restrict__ outHi,
    __nv_bfloat16* __restrict__ outLo, int ldOut,
    const float* __restrict__ cnew, float* __restrict__ snew, float* __restrict__ sF) {
    if (col >= N) return;
    v += bias[col];
    const size_t idx = (size_t)row * ldOut + col;
    if (MODE == 0) {
        float h = fmaxf(v, 0.f);
        __nv_bfloat16 hi, lo;
        split_bf16(h, hi, lo);
        outHi[idx] = hi;
        outLo[idx] = lo;
    } else if (MODE == 1) {
        outF[idx] = v;
    } else {
        const float prod = v * cnew[(size_t)(row / Tdim) * Ddim + col];
        snew[idx] = prod;
        const float s = 0.5f * sF[idx] + 0.5f * prod;
        sF[idx] = s;
        __nv_bfloat16 hi, lo;
        split_bf16(s, hi, lo);
        outHi[idx] = hi;
        outLo[idx] = lo;
    }
}

template <int MODE, bool TAIL>
__global__ void __launch_bounds__(256, 2) hmma_gemm(
    const __nv_bfloat16* __restrict__ A0hi, const __nv_bfloat16* __restrict__ A0lo, int ldA0,
    const __nv_bfloat16* __restrict__ B0hi, const __nv_bfloat16* __restrict__ B0lo,
    const float* __restrict__ bias0, int N, int K,
    float* __restrict__ outF, __nv_bfloat16* __restrict__ out0Hi,
    __nv_bfloat16* __restrict__ out0Lo, int ldOut0,
    const float* __restrict__ cnew, float* __restrict__ snew, float* __restrict__ sF,
    int yS,
    const __nv_bfloat16* __restrict__ A1hi, const __nv_bfloat16* __restrict__ A1lo, int ldA1,
    const __nv_bfloat16* __restrict__ B1hi, const __nv_bfloat16* __restrict__ B1lo,
    const float* __restrict__ bias1,
    __nv_bfloat16* __restrict__ out1Hi, __nv_bfloat16* __restrict__ out1Lo, int ldOut1) {
    extern __shared__ char smem[];
    const uint32_t sb = smem_to_u32(smem);
    const int tid = threadIdx.x;
    const int wid = tid >> 5;
    const int lid = tid & 31;
    const int wm = wid & 1;   // 0..1
    const int wn = wid >> 1;  // 0..3

    const bool p1 = ((int)blockIdx.y >= yS);
    const int bm = (p1 ? (int)blockIdx.y - yS : (int)blockIdx.y) * 128;
    const int bn = blockIdx.x * 128;
    const __nv_bfloat16* Ahi = p1 ? A1hi : A0hi;
    const __nv_bfloat16* Alo = p1 ? A1lo : A0lo;
    const __nv_bfloat16* Bhi = p1 ? B1hi : B0hi;
    const __nv_bfloat16* Blo = p1 ? B1lo : B0lo;
    const float* bias = p1 ? bias1 : bias0;
    const int ldA = p1 ? ldA1 : ldA0;
    const int ldOut = p1 ? ldOut1 : ldOut0;
    __nv_bfloat16* outHi = p1 ? out1Hi : out0Hi;
    __nv_bfloat16* outLo = p1 ? out1Lo : out0Lo;

    // per-warp valid n-fragment count; compile-time full when !TAIL
    int ntmax = 4, pmax = 2;
    if (TAIL) {
        ntmax = (N - bn - wn * 32 + 7) >> 3;
        ntmax = ntmax < 0 ? 0 : (ntmax > 4 ? 4 : ntmax);
        pmax = (ntmax + 1) >> 1;
    }

    float acc[4][4][4];
#pragma unroll
    for (int i = 0; i < 4; i++)
#pragma unroll
        for (int j = 0; j < 4; j++)
#pragma unroll
            for (int e = 0; e < 4; e++) acc[i][j][e] = 0.f;

    const int niters = K >> 5;

    // ---- stage loader: 8 cp.async / thread ----
    auto stage_load = [&](int stage, int k0) {
        const uint32_t st = sb + stage * STAGE_B;
        const int cid0 = tid * 2;
#pragma unroll
        for (int i = 0; i < 2; i++) {
            const int cid = cid0 + i;
            const int row = cid >> 2;
            const int c = cid & 3;
            const uint32_t soff = row * ROWB + c * 16;
            const size_t ga = (size_t)(bm + row) * ldA + k0 + c * 8;
            cp16(st + OFF_AHI + soff, Ahi + ga);
            cp16(st + OFF_ALO + soff, Alo + ga);
            const int n = bn + row;
            const int zf = (n < N) ? 16 : 0;
            const size_t gb = (size_t)(n < N ? n : 0) * K + k0 + c * 8;
            cp16z(st + OFF_BHI + soff, Bhi + gb, zf);
            cp16z(st + OFF_BLO + soff, Blo + gb, zf);
        }
    };

    stage_load(0, 0);
    CP_COMMIT();
    if (niters > 1) stage_load(1, 32);
    CP_COMMIT();

    // lane addressing for ldmatrix (loop-invariant)
    const int ar = wm * 64 + (lid & 15);
    const int br = wn * 32 + (lid & 7) + ((lid & 16) ? 8 : 0);

    for (int it = 0; it < niters; ++it) {
        CP_WAIT1();
        __syncthreads();

        const uint32_t st = sb + (it & 1) * STAGE_B;
        const uint32_t aHi = st + OFF_AHI, aLo = st + OFF_ALO;
        const uint32_t bHi = st + OFF_BHI, bLo = st + OFF_BLO;

#pragma unroll
        for (int ks = 0; ks < 2; ks++) {
            const int k0 = ks * 16;
            const int ak = k0 + ((lid >> 4) << 3);
            const int bk = k0 + ((lid & 8) ? 8 : 0);

            uint32_t bfh[4][2], bfl[4][2];
#pragma unroll
            for (int p = 0; p < 2; p++) {
                if (!TAIL || p < pmax) {
                    const uint32_t bo = (uint32_t)((br + p * 16) * ROWB + bk * 2);
                    uint32_t r[4];
                    ldm_x4(r, bHi + bo);
                    bfh[2 * p][0] = r[0]; bfh[2 * p][1] = r[1];
                    bfh[2 * p + 1][0] = r[2]; bfh[2 * p + 1][1] = r[3];
                    ldm_x4(r, bLo + bo);
                    bfl[2 * p][0] = r[0]; bfl[2 * p][1] = r[1];
                    bfl[2 * p + 1][0] = r[2]; bfl[2 * p + 1][1] = r[3];
                }
            }
            // A fragments loaded per-mt to cap register liveness
#pragma unroll
            for (int mt = 0; mt < 4; mt++) {
                if (!TAIL || ntmax > 0) {
                    const uint32_t ao = (uint32_t)((ar + mt * 16) * ROWB + ak * 2);
                    uint32_t ah[4], al[4];
                    ldm_x4(ah, aHi + ao);
                    ldm_x4(al, aLo + ao);
#pragma unroll
                    for (int nt = 0; nt < 4; nt++) {
                        if (!TAIL || nt < ntmax) {
                            mma_bf16(acc[mt][nt], ah, bfh[nt]);
                            mma_bf16(acc[mt][nt], ah, bfl[nt]);
                            mma_bf16(acc[mt][nt], al, bfh[nt]);
                        }
                    }
                }
            }
        }
        __syncthreads();

        // refill the buffer just consumed (stage (it+2)&1 == it&1)
        if (it + 2 < niters) stage_load(it & 1, (it + 2) * 32);
        CP_COMMIT();
    }

    // ---- epilogue: direct register -> global ----
#pragma unroll
    for (int mt = 0; mt < 4; mt++) {
        const int row0 = bm + wm * 64 + mt * 16 + (lid >> 2);
#pragma unroll
        for (int nt = 0; nt < 4; nt++) {
            if (TAIL && nt >= ntmax) continue;
            const int col0 = bn + wn * 32 + nt * 8 + 2 * (lid & 3);
            if (p1) {
                emit_elem<0>(row0, col0, N, acc[mt][nt][0], bias, outF, outHi, outLo, ldOut, cnew, snew, sF);
                emit_elem<0>(row0, col0 + 1, N, acc[mt][nt][1], bias, outF, outHi, outLo, ldOut, cnew, snew, sF);
                emit_elem<0>(row0 + 8, col0, N, acc[mt][nt][2], bias, outF, outHi, outLo, ldOut, cnew, snew, sF);
                emit_elem<0>(row0 + 8, col0 + 1, N, acc[mt][nt][3], bias, outF, outHi, outLo, ldOut, cnew, snew, sF);
            } else {
                emit_elem<MODE>(row0, col0, N, acc[mt][nt][0], bias, outF, outHi, outLo, ldOut, cnew, snew, sF);
                emit_elem<MODE>(row0, col0 + 1, N, acc[mt][nt][1], bias, outF, outHi, outLo, ldOut, cnew, snew, sF);
                emit_elem<MODE>(row0 + 8, col0, N, acc[mt][nt][2], bias, outF, outHi, outLo, ldOut, cnew, snew, sF);
                emit_elem<MODE>(row0 + 8, col0 + 1, N, acc[mt][nt][3], bias, outF, outHi, outLo, ldOut, cnew, snew, sF);
            }
        }
    }
}

// ---------------------------------------------------------------------------
// iter-0 s-shortcut: S is broadcast(anchor) -> mlp2(S) has only T=6 unique rows.
// ---------------------------------------------------------------------------
__global__ void smlp0(const float* __restrict__ anchor,
                      const float* __restrict__ sW1, const float* __restrict__ sb1,
                      const float* __restrict__ sW2, const float* __restrict__ sb2,
                      float* __restrict__ SM) {
    __shared__ float hsm[Ddim];
    const int t = blockIdx.x;
    const int d = threadIdx.x;
    float h = sb1[d];
    for (int k = 0; k < Ddim; k++)
        h = fmaf(anchor[t * Ddim + k], sW1[(size_t)k * Ddim + d], h);
    hsm[d] = fmaxf(h, 0.f);
    __syncthreads();
    float o = sb2[d];
    for (int k = 0; k < Ddim; k++)
        o = fmaf(hsm[k], sW2[(size_t)k * Ddim + d], o);
    SM[t * Ddim + d] = o;
}

// fused iter-0 tail: per (ba,d) computes all T products in-register:
// S = .5S+.5prod (+hi/lo), C = .5C+.5max_t (+hi/lo). No SNEW round-trip.
__global__ void iter0_all(const float* __restrict__ SM, const float* __restrict__ CNEW,
                          float* __restrict__ S, __nv_bfloat16* __restrict__ Shi,
                          __nv_bfloat16* __restrict__ Slo, float* __restrict__ C,
                          __nv_bfloat16* __restrict__ Chi, __nv_bfloat16* __restrict__ Clo) {
    const long i = (long)blockIdx.x * blockDim.x + threadIdx.x;
    if (i >= (long)BAn * Ddim) return;
    const long ba = i >> 8;
    const int d = (int)(i & (Ddim - 1));
    const float c = CNEW[i];
    float m = -3.4e38f;
#pragma unroll
    for (int t = 0; t < Tdim; t++) {
        const float prod = SM[t * Ddim + d] * c;
        m = fmaxf(m, prod);
        const size_t idx = (size_t)(ba * Tdim + t) * Ddim + d;
        const float s = 0.5f * S[idx] + 0.5f * prod;
        S[idx] = s;
        __nv_bfloat16 hi, lo;
        split_bf16(s, hi, lo);
        Shi[idx] = hi;
        Slo[idx] = lo;
    }
    const float v = 0.5f * C[i] + 0.5f * m;
    C[i] = v;
    __nv_bfloat16 hi, lo;
    split_bf16(v, hi, lo);
    Chi[i] = hi;
    Clo[i] = lo;
}

// ---------------------------------------------------------------------------
// weight transpose + bf16 split: W[K][N] -> WT_hi/lo[N][K]
// ---------------------------------------------------------------------------
__global__ void wtrans_banked(const float* __restrict__ sW1, const float* __restrict__ sW2,
                              const float* __restrict__ cW1, const float* __restrict__ cW2,
                              __nv_bfloat16* __restrict__ Thi, __nv_bfloat16* __restrict__ Tlo) {
    __shared__ float t[32][33];
    const int z = blockIdx.z;
    const int tensor = z / NBdim, bank = z % NBdim;
    const float* src = (tensor == 0 ? sW1 : tensor == 1 ? sW2 : tensor == 2 ? cW1 : cW2) +
                       (size_t)bank * Ddim * Ddim;
    const size_t dof = (size_t)tensor * (NBdim * Ddim * Ddim) + (size_t)bank * Ddim * Ddim;
    const int k0 = blockIdx.x * 32, n0 = blockIdx.y * 32;
    const int tx = threadIdx.x, ty = threadIdx.y;
#pragma unroll
    for (int i = 0; i < 4; i++)
        t[ty + i * 8][tx] = src[(size_t)(k0 + ty + i * 8) * Ddim + n0 + tx];
    __syncthreads();
#pragma unroll
    for (int i = 0; i < 4; i++) {
        const int n = n0 + ty + i * 8, k = k0 + tx;
        __nv_bfloat16 hi, lo;
        split_bf16(t[tx][ty + i * 8], hi, lo);
        Thi[dof + (size_t)n * Ddim + k] = hi;
        Tlo[dof + (size_t)n * Ddim + k] = lo;
    }
}

__global__ void wtrans_single(const float* __restrict__ W, int K, int N,
                              __nv_bfloat16* __restrict__ Thi, __nv_bfloat16* __restrict__ Tlo) {
    __shared__ float t[32][33];
    const int k0 = blockIdx.x * 32, n0 = blockIdx.y * 32;
    const int tx = threadIdx.x, ty = threadIdx.y;
#pragma unroll
    for (int i = 0; i < 4; i++) {
        const int k = k0 + ty + i * 8;
        t[ty + i * 8][tx] = (n0 + tx < N) ? W[(size_t)k * N + n0 + tx] : 0.f;
    }
    __syncthreads();
#pragma unroll
    for (int i = 0; i < 4; i++) {
        const int n = n0 + ty + i * 8, k = k0 + tx;
        if (n < N) {
            __nv_bfloat16 hi, lo;
            split_bf16(t[tx][ty + i * 8], hi, lo);
            Thi[(size_t)n * K + k] = hi;
            Tlo[(size_t)n * K + k] = lo;
        }
    }
}

// ---------------------------------------------------------------------------
__global__ void init_kernel(const float* __restrict__ fe, const float* __restrict__ anchor,
                            float* __restrict__ S, __nv_bfloat16* __restrict__ Shi,
                            __nv_bfloat16* __restrict__ Slo, float* __restrict__ C,
                            __nv_bfloat16* __restrict__ Chi, __nv_bfloat16* __restrict__ Clo) {
    const long i = (long)blockIdx.x * blockDim.x + threadIdx.x;
    if (i < (long)ROWS * Ddim) {
        const int d = (int)(i & (Ddim - 1));
        const int t = (int)((i >> 8) % Tdim);
        const float v = anchor[t * Ddim + d];
        S[i] = v;
        __nv_bfloat16 hi, lo;
        split_bf16(v, hi, lo);
        Shi[i] = hi;
        Slo[i] = lo;
    }
    if (i < (long)BAn * Ddim) {
        const float v = fe[i];
        C[i] = v;
        __nv_bfloat16 hi, lo;
        split_bf16(v, hi, lo);
        Chi[i] = hi;
        Clo[i] = lo;
    }
}

__global__ void agg_update_c(const float* __restrict__ snew, float* __restrict__ C,
                             __nv_bfloat16* __restrict__ Chi, __nv_bfloat16* __restrict__ Clo) {
    const long i = (long)blockIdx.x * blockDim.x + threadIdx.x;
    if (i >= (long)BAn * Ddim) return;
    const long ba = i >> 8;
    const int d = (int)(i & (Ddim - 1));
    const float* p = snew + ba * Tdim * Ddim + d;
    float m = p[0];
#pragma unroll
    for (int t = 1; t < Tdim; t++) m = fmaxf(m, p[t * Ddim]);
    const float v = 0.5f * C[i] + 0.5f * m;
    C[i] = v;
    __nv_bfloat16 hi, lo;
    split_bf16(v, hi, lo);
    Chi[i] = hi;
    Clo[i] = lo;
}

__global__ void decode_out(const float* __restrict__ res, float* __restrict__ out) {
    const long i = (long)blockIdx.x * blockDim.x + threadIdx.x;
    if (i >= (long)ROWS * 80) return;
    const long row = i / 80;
    const int j = (int)(i % 80);
    const float* r = res + row * OUTdim;

    float* coords = out + ROWS;
    coords[row * 160 + 2 * j + 0] = r[2 * j + 0];
    coords[row * 160 + 2 * j + 1] = r[2 * j + 1];

    const float av = r[160 + j], bv = r[240 + j], cv = r[320 + j];
    const float ecv = expf(cv);
    const float ch = coshf(bv) * ecv;
    const float sh = sinhf(bv) * ecv;
    float* cov = out + ROWS + (long)ROWS * 160;
    const long cb = row * 320 + (long)j * 4;
    cov[cb + 0] = expf(av) * ch;
    cov[cb + 1] = sh;
    cov[cb + 2] = sh;
    cov[cb + 3] = expf(-av) * ch;

    if (j == 0) out[row] = r[400];
}

// ---------------------------------------------------------------------------
extern "C" void kernel_launch(void* const* d_in, const int* in_sizes, int n_in,
                              void* d_out, int out_size) {
    const float* fe = (const float*)d_in[0];
    const float* anchor = (const float*)d_in[1];
    const float* sW1 = (const float*)d_in[2];
    const float* sb1 = (const float*)d_in[3];
    const float* sW2 = (const float*)d_in[4];
    const float* sb2 = (const float*)d_in[5];
    const float* cW1 = (const float*)d_in[6];
    const float* cb1 = (const float*)d_in[7];
    const float* cW2 = (const float*)d_in[8];
    const float* cb2 = (const float*)d_in[9];
    const float* dW1 = (const float*)d_in[10];
    const float* db1 = (const float*)d_in[11];
    const float* dW2 = (const float*)d_in[12];
    const float* db2 = (const float*)d_in[13];
    float* out = (float*)d_out;

    float *S, *SNEW, *C, *CNEW, *RES, *SM0;
    __nv_bfloat16 *Hhi, *Hlo, *HChi, *HClo, *Shi, *Slo, *Chi, *Clo, *WThi, *WTlo;
    cudaGetSymbolAddress((void**)&S, g_S);
    cudaGetSymbolAddress((void**)&SNEW, g_SNEW);
    cudaGetSymbolAddress((void**)&C, g_C);
    cudaGetSymbolAddress((void**)&CNEW, g_CNEW);
    cudaGetSymbolAddress((void**)&RES, g_RES);
    cudaGetSymbolAddress((void**)&SM0, g_SM0);
    cudaGetSymbolAddress((void**)&Hhi, g_Hhi);
    cudaGetSymbolAddress((void**)&Hlo, g_Hlo);
    cudaGetSymbolAddress((void**)&HChi, g_HChi);
    cudaGetSymbolAddress((void**)&HClo, g_HClo);
    cudaGetSymbolAddress((void**)&Shi, g_Shi);
    cudaGetSymbolAddress((void**)&Slo, g_Slo);
    cudaGetSymbolAddress((void**)&Chi, g_Chi);
    cudaGetSymbolAddress((void**)&Clo, g_Clo);
    cudaGetSymbolAddress((void**)&WThi, g_WThi);
    cudaGetSymbolAddress((void**)&WTlo, g_WTlo);

    cudaFuncSetAttribute((const void*)hmma_gemm<0, false>, cudaFuncAttributeMaxDynamicSharedMemorySize, GEMM_SMEM);
    cudaFuncSetAttribute((const void*)hmma_gemm<1, false>, cudaFuncAttributeMaxDynamicSharedMemorySize, GEMM_SMEM);
    cudaFuncSetAttribute((const void*)hmma_gemm<2, false>, cudaFuncAttributeMaxDynamicSharedMemorySize, GEMM_SMEM);
    cudaFuncSetAttribute((const void*)hmma_gemm<1, true>, cudaFuncAttributeMaxDynamicSharedMemorySize, GEMM_SMEM);

    // prep (smlp0 first so the first hmma_gemm lands early in node order for ncu)
    smlp0<<<Tdim, Ddim>>>(anchor, sW1, sb1, sW2, sb2, SM0); // bank-0 weights, fp32 inputs
    wtrans_banked<<<dim3(8, 8, 4 * NBdim), dim3(32, 8)>>>(sW1, sW2, cW1, cW2, WThi, WTlo);
    wtrans_single<<<dim3(8, 16), dim3(32, 8)>>>(dW1, Ddim, Hdim, WThi + WOFF_DW1, WTlo + WOFF_DW1);
    wtrans_single<<<dim3(16, 13), dim3(32, 8)>>>(dW2, Hdim, OUTdim, WThi + WOFF_DW2, WTlo + WOFF_DW2);

    const long NS = (long)ROWS * Ddim;
    init_kernel<<<(unsigned)((NS + 255) / 256), 256>>>(fe, anchor, S, Shi, Slo, C, Chi, Clo);

    const int BIG = 1 << 30;
    const dim3 grid1(2, ROWS / 128 + BAn / 128); // batched sG1 + cG1 (iters >= 1)
    const dim3 gridC(2, BAn / 128);              // c-GEMMs
    const dim3 gridS(2, ROWS / 128);             // sG2
    const dim3 gridD1(4, ROWS / 128);            // decoder1 N=512
    const dim3 gridD2(4, ROWS / 128);            // decoder2 N=401 (TAIL-skipped)

    for (int i = 0; i < NBdim; i++) {
        const size_t wo = (size_t)i * Ddim * Ddim;
        const int bo = i * Ddim;
        if (i == 0) {
            // iter 0: s path collapses to 6 unique rows (S = broadcast anchor)
            hmma_gemm<0, false><<<gridC, 256, GEMM_SMEM>>>(
                Chi, Clo, Ddim, WThi + WOFF_CW1 + wo, WTlo + WOFF_CW1 + wo, cb1 + bo,
                Ddim, Ddim, nullptr, HChi, HClo, Hdim, nullptr, nullptr, nullptr,
                BIG, nullptr, nullptr, 0, nullptr, nullptr, nullptr, nullptr, nullptr, 0);
            hmma_gemm<1, false><<<gridC, 256, GEMM_SMEM>>>(
                HChi, HClo, Hdim, WThi + WOFF_CW2 + wo, WTlo + WOFF_CW2 + wo, cb2 + bo,
                Ddim, Ddim, CNEW, nullptr, nullptr, Ddim, nullptr, nullptr, nullptr,
                BIG, nullptr, nullptr, 0, nullptr, nullptr, nullptr, nullptr, nullptr, 0);
            iter0_all<<<(BAn * Ddim + 255) / 256, 256>>>(SM0, CNEW, S, Shi, Slo, C, Chi, Clo);
        } else {
            // batched: s_hidden (relu) -> Hhi/Hlo || c_hidden (relu) -> HChi/HClo
            hmma_gemm<0, false><<<grid1, 256, GEMM_SMEM>>>(
                Shi, Slo, Ddim, WThi + WOFF_SW1 + wo, WTlo + WOFF_SW1 + wo, sb1 + bo,
                Ddim, Ddim, nullptr, Hhi, Hlo, Hdim, nullptr, nullptr, nullptr,
                ROWS / 128,
                Chi, Clo, Ddim, WThi + WOFF_CW1 + wo, WTlo + WOFF_CW1 + wo, cb1 + bo,
                HChi, HClo, Hdim);
            hmma_gemm<1, false><<<gridC, 256, GEMM_SMEM>>>(
                HChi, HClo, Hdim, WThi + WOFF_CW2 + wo, WTlo + WOFF_CW2 + wo, cb2 + bo,
                Ddim, Ddim, CNEW, nullptr, nullptr, Ddim, nullptr, nullptr, nullptr,
                BIG, nullptr, nullptr, 0, nullptr, nullptr, nullptr, nullptr, nullptr, 0);
            hmma_gemm<2, false><<<gridS, 256, GEMM_SMEM>>>(
                Hhi, Hlo, Hdim, WThi + WOFF_SW2 + wo, WTlo + WOFF_SW2 + wo, sb2 + bo,
                Ddim, Ddim, nullptr, Shi, Slo, Ddim, CNEW, SNEW, S,
                BIG, nullptr, nullptr, 0, nullptr, nullptr, nullptr, nullptr, nullptr, 0);
            agg_update_c<<<(BAn * Ddim + 255) / 256, 256>>>(SNEW, C, Chi, Clo);
        }
    }

    // decoder
    hmma_gemm<0, false><<<gridD1, 256, GEMM_SMEM>>>(
        Shi, Slo, Ddim, WThi + WOFF_DW1, WTlo + WOFF_DW1, db1,
        Hdim, Ddim, nullptr, Hhi, Hlo, Hdim, nullptr, nullptr, nullptr,
        BIG, nullptr, nullptr, 0, nullptr, nullptr, nullptr, nullptr, nullptr, 0);
    hmma_gemm<1, true><<<gridD2, 256, GEMM_SMEM>>>(
        Hhi, Hlo, Hdim, WThi + WOFF_DW2, WTlo + WOFF_DW2, db2,
        OUTdim, Hdim, RES, nullptr, nullptr, OUTdim, nullptr, nullptr, nullptr,
        BIG, nullptr, nullptr, 0, nullptr, nullptr, nullptr, nullptr, nullptr, 0);

    decode_out<<<(unsigned)(((long)ROWS * 80 + 255) / 256), 256>>>(RES, out);
}

// round 17
// speedup vs baseline: 1.0915x; 1.0266x over previous
#include <cuda_runtime.h>
#include <cuda_bf16.h>
#include <cstdint>

#define Bdim 64
#define Adim 128
#define Tdim 6
#define Ddim 256
#define Hdim 512
#define NBdim 5
#define OUTdim 401

#define ROWS (Bdim * Adim * Tdim) /* 49152 */
#define BAn (Bdim * Adim)         /* 8192  */

// ---------------- scratch (__device__ globals; allocation-free rule) -------
__device__ float g_S[ROWS * Ddim];
__device__ float g_SNEW[ROWS * Ddim];
__device__ float g_C[BAn * Ddim];
__device__ float g_CNEW[BAn * Ddim];
__device__ float g_RES[ROWS * OUTdim];
__device__ float g_SM0[Tdim * Ddim]; // iter-0 s-MLP (6 unique rows)

__device__ __nv_bfloat16 g_Hhi[ROWS * Hdim];
__device__ __nv_bfloat16 g_Hlo[ROWS * Hdim];
__device__ __nv_bfloat16 g_HChi[BAn * Hdim];
__device__ __nv_bfloat16 g_HClo[BAn * Hdim];
__device__ __nv_bfloat16 g_Shi[ROWS * Ddim];
__device__ __nv_bfloat16 g_Slo[ROWS * Ddim];
__device__ __nv_bfloat16 g_Chi[BAn * Ddim];
__device__ __nv_bfloat16 g_Clo[BAn * Ddim];

// transposed+split weights: WT[N][K] bf16 (hi and lo arrays)
#define WOFF_SW1 0
#define WOFF_SW2 327680
#define WOFF_CW1 655360
#define WOFF_CW2 983040
#define WOFF_DW1 1310720
#define WOFF_DW2 1441792
#define WTOT     1647104
__device__ __nv_bfloat16 g_WThi[WTOT];
__device__ __nv_bfloat16 g_WTlo[WTOT];

// ---------------- helpers --------------------------------------------------
__device__ __forceinline__ uint32_t smem_to_u32(const void* p) {
    uint32_t a;
    asm("{ .reg .u64 t; cvta.to.shared.u64 t, %1; cvt.u32.u64 %0, t; }"
        : "=r"(a) : "l"(p));
    return a;
}
__device__ __forceinline__ void cp16(uint32_t dst, const void* src) {
    asm volatile("cp.async.cg.shared.global [%0], [%1], 16;"
                 :: "r"(dst), "l"(src));
}
__device__ __forceinline__ void cp16z(uint32_t dst, const void* src, int zf) {
    asm volatile("cp.async.cg.shared.global [%0], [%1], 16, %2;"
                 :: "r"(dst), "l"(src), "r"(zf));
}
#define CP_COMMIT() asm volatile("cp.async.commit_group;" ::: "memory")
#define CP_WAIT1()  asm volatile("cp.async.wait_group 1;" ::: "memory")

__device__ __forceinline__ void ldm_x4(uint32_t* r, uint32_t addr) {
    asm volatile("ldmatrix.sync.aligned.m8n8.x4.shared.b16 {%0,%1,%2,%3}, [%4];"
                 : "=r"(r[0]), "=r"(r[1]), "=r"(r[2]), "=r"(r[3]) : "r"(addr));
}
__device__ __forceinline__ void mma_bf16(float* c, const uint32_t* a, const uint32_t* b) {
    asm volatile(
        "mma.sync.aligned.m16n8k16.row.col.f32.bf16.bf16.f32 "
        "{%0,%1,%2,%3},{%4,%5,%6,%7},{%8,%9},{%0,%1,%2,%3};"
        : "+f"(c[0]), "+f"(c[1]), "+f"(c[2]), "+f"(c[3])
        : "r"(a[0]), "r"(a[1]), "r"(a[2]), "r"(a[3]), "r"(b[0]), "r"(b[1]));
}
__device__ __forceinline__ void split_bf16(float v, __nv_bfloat16& hi, __nv_bfloat16& lo) {
    hi = __float2bfloat16(v);
    lo = __float2bfloat16(v - __bfloat162float(hi));
}

// ---------------------------------------------------------------------------
// HMMA GEMM: out[M,N] = A[M,K] @ WT[N,K]^T (+bias), bf16 hi/lo 3-term split.
// Tile 128x128x32, 256 thr (8 warps, 2x4), warp tile 64x32.
// 2-stage cp.async double buffer; __launch_bounds__(256,2) -> 2 CTAs/SM.
// TAIL template flag: compile-time 0 keeps the clean R12 mainloop; TAIL=1
// (decoder-2 N-tail launch only) skips OOB n-fragment groups.
// xOff: x-block offset so a tail launch can cover a column sub-range.
// Dual-problem batching via yS (problem 1 uses MODE-0 epilogue).
// MODE 0: relu -> bf16 hi/lo; MODE 1: fp32; MODE 2: snew/s-update fused;
// MODE 3: decoder-2 fused output (coords/probas direct to out via snew ptr,
//         mid cols (av/bv/cv block) to RES via outF).
// ---------------------------------------------------------------------------
#define ROWB 80
#define OFF_AHI 0
#define OFF_ALO 10240
#define OFF_BHI 20480
#define OFF_BLO 30720
#define STAGE_B 40960
#define NSTAGE 2
#define GEMM_SMEM (NSTAGE * STAGE_B)

template <int MODE>
__device__ __forceinline__ void emit_elem(
    int row, int col, int N, float v, const float* __restrict__ bias,
    float* __restrict__ outF, __nv_bfloat16* __restrict__ outHi,
    __nv_bfloat16* __restrict__ outLo, int ldOut,
    const float* __restrict__ cnew, float* __restrict__ snew, float* __restrict__ sF) {
    if (col >= N) return;
    v += bias[col];
    if (MODE == 3) {
        // decoder-2 fused: snew carries d_out base pointer
        if (col < 160) {
            snew[(size_t)ROWS + (size_t)row * 160 + col] = v;        // coords
        } else if (col >= 400) {
            snew[row] = v;                                           // probas
        } else {
            outF[(size_t)row * OUTdim + col] = v;                    // RES (av/bv/cv)
        }
        return;
    }
    const size_t idx = (size_t)row * ldOut + col;
    if (MODE == 0) {
        float h = fmaxf(v, 0.f);
        __nv_bfloat16 hi, lo;
        split_bf16(h, hi, lo);
        outHi[idx] = hi;
        outLo[idx] = lo;
    } else if (MODE == 1) {
        outF[idx] = v;
    } else {
        const float prod = v * cnew[(size_t)(row / Tdim) * Ddim + col];
        snew[idx] = prod;
        const float s = 0.5f * sF[idx] + 0.5f * prod;
        sF[idx] = s;
        __nv_bfloat16 hi, lo;
        split_bf16(s, hi, lo);
        outHi[idx] = hi;
        outLo[idx] = lo;
    }
}

template <int MODE, bool TAIL>
__global__ void __launch_bounds__(256, 2) hmma_gemm(
    const __nv_bfloat16* __restrict__ A0hi, const __nv_bfloat16* __restrict__ A0lo, int ldA0,
    const __nv_bfloat16* __restrict__ B0hi, const __nv_bfloat16* __restrict__ B0lo,
    const float* __restrict__ bias0, int N, int K,
    float* __restrict__ outF, __nv_bfloat16* __restrict__ out0Hi,
    __nv_bfloat16* __restrict__ out0Lo, int ldOut0,
    const float* __restrict__ cnew, float* __restrict__ snew, float* __restrict__ sF,
    int yS, int xOff,
    const __nv_bfloat16* __restrict__ A1hi, const __nv_bfloat16* __restrict__ A1lo, int ldA1,
    const __nv_bfloat16* __restrict__ B1hi, const __nv_bfloat16* __restrict__ B1lo,
    const float* __restrict__ bias1,
    __nv_bfloat16* __restrict__ out1Hi, __nv_bfloat16* __restrict__ out1Lo, int ldOut1) {
    extern __shared__ char smem[];
    const uint32_t sb = smem_to_u32(smem);
    const int tid = threadIdx.x;
    const int wid = tid >> 5;
    const int lid = tid & 31;
    const int wm = wid & 1;   // 0..1
    const int wn = wid >> 1;  // 0..3

    const bool p1 = ((int)blockIdx.y >= yS);
    const int bm = (p1 ? (int)blockIdx.y - yS : (int)blockIdx.y) * 128;
    const int bn = ((int)blockIdx.x + xOff) * 128;
    const __nv_bfloat16* Ahi = p1 ? A1hi : A0hi;
    const __nv_bfloat16* Alo = p1 ? A1lo : A0lo;
    const __nv_bfloat16* Bhi = p1 ? B1hi : B0hi;
    const __nv_bfloat16* Blo = p1 ? B1lo : B0lo;
    const float* bias = p1 ? bias1 : bias0;
    const int ldA = p1 ? ldA1 : ldA0;
    const int ldOut = p1 ? ldOut1 : ldOut0;
    __nv_bfloat16* outHi = p1 ? out1Hi : out0Hi;
    __nv_bfloat16* outLo = p1 ? out1Lo : out0Lo;

    // per-warp valid n-fragment count; compile-time full when !TAIL
    int ntmax = 4, pmax = 2;
    if (TAIL) {
        ntmax = (N - bn - wn * 32 + 7) >> 3;
        ntmax = ntmax < 0 ? 0 : (ntmax > 4 ? 4 : ntmax);
        pmax = (ntmax + 1) >> 1;
    }

    float acc[4][4][4];
#pragma unroll
    for (int i = 0; i < 4; i++)
#pragma unroll
        for (int j = 0; j < 4; j++)
#pragma unroll
            for (int e = 0; e < 4; e++) acc[i][j][e] = 0.f;

    const int niters = K >> 5;

    // ---- stage loader: 8 cp.async / thread ----
    auto stage_load = [&](int stage, int k0) {
        const uint32_t st = sb + stage * STAGE_B;
        const int cid0 = tid * 2;
#pragma unroll
        for (int i = 0; i < 2; i++) {
            const int cid = cid0 + i;
            const int row = cid >> 2;
            const int c = cid & 3;
            const uint32_t soff = row * ROWB + c * 16;
            const size_t ga = (size_t)(bm + row) * ldA + k0 + c * 8;
            cp16(st + OFF_AHI + soff, Ahi + ga);
            cp16(st + OFF_ALO + soff, Alo + ga);
            const int n = bn + row;
            const int zf = (n < N) ? 16 : 0;
            const size_t gb = (size_t)(n < N ? n : 0) * K + k0 + c * 8;
            cp16z(st + OFF_BHI + soff, Bhi + gb, zf);
            cp16z(st + OFF_BLO + soff, Blo + gb, zf);
        }
    };

    stage_load(0, 0);
    CP_COMMIT();
    if (niters > 1) stage_load(1, 32);
    CP_COMMIT();

    // lane addressing for ldmatrix (loop-invariant)
    const int ar = wm * 64 + (lid & 15);
    const int br = wn * 32 + (lid & 7) + ((lid & 16) ? 8 : 0);

    for (int it = 0; it < niters; ++it) {
        CP_WAIT1();
        __syncthreads();

        const uint32_t st = sb + (it & 1) * STAGE_B;
        const uint32_t aHi = st + OFF_AHI, aLo = st + OFF_ALO;
        const uint32_t bHi = st + OFF_BHI, bLo = st + OFF_BLO;

#pragma unroll
        for (int ks = 0; ks < 2; ks++) {
            const int k0 = ks * 16;
            const int ak = k0 + ((lid >> 4) << 3);
            const int bk = k0 + ((lid & 8) ? 8 : 0);

            uint32_t bfh[4][2], bfl[4][2];
#pragma unroll
            for (int p = 0; p < 2; p++) {
                if (!TAIL || p < pmax) {
                    const uint32_t bo = (uint32_t)((br + p * 16) * ROWB + bk * 2);
                    uint32_t r[4];
                    ldm_x4(r, bHi + bo);
                    bfh[2 * p][0] = r[0]; bfh[2 * p][1] = r[1];
                    bfh[2 * p + 1][0] = r[2]; bfh[2 * p + 1][1] = r[3];
                    ldm_x4(r, bLo + bo);
                    bfl[2 * p][0] = r[0]; bfl[2 * p][1] = r[1];
                    bfl[2 * p + 1][0] = r[2]; bfl[2 * p + 1][1] = r[3];
                }
            }
            // A fragments loaded per-mt to cap register liveness
#pragma unroll
            for (int mt = 0; mt < 4; mt++) {
                if (!TAIL || ntmax > 0) {
                    const uint32_t ao = (uint32_t)((ar + mt * 16) * ROWB + ak * 2);
                    uint32_t ah[4], al[4];
                    ldm_x4(ah, aHi + ao);
                    ldm_x4(al, aLo + ao);
#pragma unroll
                    for (int nt = 0; nt < 4; nt++) {
                        if (!TAIL || nt < ntmax) {
                            mma_bf16(acc[mt][nt], ah, bfh[nt]);
                            mma_bf16(acc[mt][nt], ah, bfl[nt]);
                            mma_bf16(acc[mt][nt], al, bfh[nt]);
                        }
                    }
                }
            }
        }
        __syncthreads();

        // refill the buffer just consumed (stage (it+2)&1 == it&1)
        if (it + 2 < niters) stage_load(it & 1, (it + 2) * 32);
        CP_COMMIT();
    }

    // ---- epilogue: direct register -> global ----
#pragma unroll
    for (int mt = 0; mt < 4; mt++) {
        const int row0 = bm + wm * 64 + mt * 16 + (lid >> 2);
#pragma unroll
        for (int nt = 0; nt < 4; nt++) {
            if (TAIL && nt >= ntmax) continue;
            const int col0 = bn + wn * 32 + nt * 8 + 2 * (lid & 3);
            if (p1) {
                emit_elem<0>(row0, col0, N, acc[mt][nt][0], bias, outF, outHi, outLo, ldOut, cnew, snew, sF);
                emit_elem<0>(row0, col0 + 1, N, acc[mt][nt][1], bias, outF, outHi, outLo, ldOut, cnew, snew, sF);
                emit_elem<0>(row0 + 8, col0, N, acc[mt][nt][2], bias, outF, outHi, outLo, ldOut, cnew, snew, sF);
                emit_elem<0>(row0 + 8, col0 + 1, N, acc[mt][nt][3], bias, outF, outHi, outLo, ldOut, cnew, snew, sF);
            } else {
                emit_elem<MODE>(row0, col0, N, acc[mt][nt][0], bias, outF, outHi, outLo, ldOut, cnew, snew, sF);
                emit_elem<MODE>(row0, col0 + 1, N, acc[mt][nt][1], bias, outF, outHi, outLo, ldOut, cnew, snew, sF);
                emit_elem<MODE>(row0 + 8, col0, N, acc[mt][nt][2], bias, outF, outHi, outLo, ldOut, cnew, snew, sF);
                emit_elem<MODE>(row0 + 8, col0 + 1, N, acc[mt][nt][3], bias, outF, outHi, outLo, ldOut, cnew, snew, sF);
            }
        }
    }
}

// ---------------------------------------------------------------------------
// iter-0 s-shortcut: S is broadcast(anchor) -> mlp2(S) has only T=6 unique rows.
// ---------------------------------------------------------------------------
__global__ void smlp0(const float* __restrict__ anchor,
                      const float* __restrict__ sW1, const float* __restrict__ sb1,
                      const float* __restrict__ sW2, const float* __restrict__ sb2,
                      float* __restrict__ SM) {
    __shared__ float hsm[Ddim];
    const int t = blockIdx.x;
    const int d = threadIdx.x;
    float h = sb1[d];
    for (int k = 0; k < Ddim; k++)
        h = fmaf(anchor[t * Ddim + k], sW1[(size_t)k * Ddim + d], h);
    hsm[d] = fmaxf(h, 0.f);
    __syncthreads();
    float o = sb2[d];
    for (int k = 0; k < Ddim; k++)
        o = fmaf(hsm[k], sW2[(size_t)k * Ddim + d], o);
    SM[t * Ddim + d] = o;
}

// fused iter-0 tail: per (ba,d) computes all T products in-register.
// S fp32 comes straight from anchor (S was broadcast(anchor) at iter 0), so
// no S initialization pass is needed at all.
__global__ void iter0_all(const float* __restrict__ anchor,
                          const float* __restrict__ SM, const float* __restrict__ CNEW,
                          float* __restrict__ S, __nv_bfloat16* __restrict__ Shi,
                          __nv_bfloat16* __restrict__ Slo, float* __restrict__ C,
                          __nv_bfloat16* __restrict__ Chi, __nv_bfloat16* __restrict__ Clo) {
    const long i = (long)blockIdx.x * blockDim.x + threadIdx.x;
    if (i >= (long)BAn * Ddim) return;
    const long ba = i >> 8;
    const int d = (int)(i & (Ddim - 1));
    const float c = CNEW[i];
    float m = -3.4e38f;
#pragma unroll
    for (int t = 0; t < Tdim; t++) {
        const float prod = SM[t * Ddim + d] * c;
        m = fmaxf(m, prod);
        const size_t idx = (size_t)(ba * Tdim + t) * Ddim + d;
        const float s = 0.5f * anchor[t * Ddim + d] + 0.5f * prod;
        S[idx] = s;
        __nv_bfloat16 hi, lo;
        split_bf16(s, hi, lo);
        Shi[idx] = hi;
        Slo[idx] = lo;
    }
    const float v = 0.5f * C[i] + 0.5f * m;
    C[i] = v;
    __nv_bfloat16 hi, lo;
    split_bf16(v, hi, lo);
    Chi[i] = hi;
    Clo[i] = lo;
}

// ---------------------------------------------------------------------------
// weight transpose + bf16 split: W[K][N] -> WT_hi/lo[N][K]
// ---------------------------------------------------------------------------
__global__ void wtrans_banked(const float* __restrict__ sW1, const float* __restrict__ sW2,
                              const float* __restrict__ cW1, const float* __restrict__ cW2,
                              __nv_bfloat16* __restrict__ Thi, __nv_bfloat16* __restrict__ Tlo) {
    __shared__ float t[32][33];
    const int z = blockIdx.z;
    const int tensor = z / NBdim, bank = z % NBdim;
    const float* src = (tensor == 0 ? sW1 : tensor == 1 ? sW2 : tensor == 2 ? cW1 : cW2) +
                       (size_t)bank * Ddim * Ddim;
    const size_t dof = (size_t)tensor * (NBdim * Ddim * Ddim) + (size_t)bank * Ddim * Ddim;
    const int k0 = blockIdx.x * 32, n0 = blockIdx.y * 32;
    const int tx = threadIdx.x, ty = threadIdx.y;
#pragma unroll
    for (int i = 0; i < 4; i++)
        t[ty + i * 8][tx] = src[(size_t)(k0 + ty + i * 8) * Ddim + n0 + tx];
    __syncthreads();
#pragma unroll
    for (int i = 0; i < 4; i++) {
        const int n = n0 + ty + i * 8, k = k0 + tx;
        __nv_bfloat16 hi, lo;
        split_bf16(t[tx][ty + i * 8], hi, lo);
        Thi[dof + (size_t)n * Ddim + k] = hi;
        Tlo[dof + (size_t)n * Ddim + k] = lo;
    }
}

__global__ void wtrans_single(const float* __restrict__ W, int K, int N,
                              __nv_bfloat16* __restrict__ Thi, __nv_bfloat16* __restrict__ Tlo) {
    __shared__ float t[32][33];
    const int k0 = blockIdx.x * 32, n0 = blockIdx.y * 32;
    const int tx = threadIdx.x, ty = threadIdx.y;
#pragma unroll
    for (int i = 0; i < 4; i++) {
        const int k = k0 + ty + i * 8;
        t[ty + i * 8][tx] = (n0 + tx < N) ? W[(size_t)k * N + n0 + tx] : 0.f;
    }
    __syncthreads();
#pragma unroll
    for (int i = 0; i < 4; i++) {
        const int n = n0 + ty + i * 8, k = k0 + tx;
        if (n < N) {
            __nv_bfloat16 hi, lo;
            split_bf16(t[tx][ty + i * 8], hi, lo);
            Thi[(size_t)n * K + k] = hi;
            Tlo[(size_t)n * K + k] = lo;
        }
    }
}

// ---------------------------------------------------------------------------
// init: C = final_embedding (+ hi/lo). S needs no init (see iter0_all).
// ---------------------------------------------------------------------------
__global__ void init_c(const float* __restrict__ fe, float* __restrict__ C,
                       __nv_bfloat16* __restrict__ Chi, __nv_bfloat16* __restrict__ Clo) {
    const long i = (long)blockIdx.x * blockDim.x + threadIdx.x;
    if (i >= (long)BAn * Ddim) return;
    const float v = fe[i];
    C[i] = v;
    __nv_bfloat16 hi, lo;
    split_bf16(v, hi, lo);
    Chi[i] = hi;
    Clo[i] = lo;
}

__global__ void agg_update_c(const float* __restrict__ snew, float* __restrict__ C,
                             __nv_bfloat16* __restrict__ Chi, __nv_bfloat16* __restrict__ Clo) {
    const long i = (long)blockIdx.x * blockDim.x + threadIdx.x;
    if (i >= (long)BAn * Ddim) return;
    const long ba = i >> 8;
    const int d = (int)(i & (Ddim - 1));
    const float* p = snew + ba * Tdim * Ddim + d;
    float m = p[0];
#pragma unroll
    for (int t = 1; t < Tdim; t++) m = fmaxf(m, p[t * Ddim]);
    const float v = 0.5f * C[i] + 0.5f * m;
    C[i] = v;
    __nv_bfloat16 hi, lo;
    split_bf16(v, hi, lo);
    Chi[i] = hi;
    Clo[i] = lo;
}

// cov-only decode (coords/probas were written by the MODE-3 GEMM epilogue)
__global__ void decode_cov(const float* __restrict__ res, float* __restrict__ out) {
    const long i = (long)blockIdx.x * blockDim.x + threadIdx.x;
    if (i >= (long)ROWS * 80) return;
    const long row = i / 80;
    const int j = (int)(i % 80);
    const float* r = res + row * OUTdim;

    const float av = r[160 + j], bv = r[240 + j], cv = r[320 + j];
    const float ecv = expf(cv);
    const float ch = coshf(bv) * ecv;
    const float sh = sinhf(bv) * ecv;
    float* cov = out + ROWS + (long)ROWS * 160;
    const long cb = row * 320 + (long)j * 4;
    cov[cb + 0] = expf(av) * ch;
    cov[cb + 1] = sh;
    cov[cb + 2] = sh;
    cov[cb + 3] = expf(-av) * ch;
}

// ---------------------------------------------------------------------------
extern "C" void kernel_launch(void* const* d_in, const int* in_sizes, int n_in,
                              void* d_out, int out_size) {
    const float* fe = (const float*)d_in[0];
    const float* anchor = (const float*)d_in[1];
    const float* sW1 = (const float*)d_in[2];
    const float* sb1 = (const float*)d_in[3];
    const float* sW2 = (const float*)d_in[4];
    const float* sb2 = (const float*)d_in[5];
    const float* cW1 = (const float*)d_in[6];
    const float* cb1 = (const float*)d_in[7];
    const float* cW2 = (const float*)d_in[8];
    const float* cb2 = (const float*)d_in[9];
    const float* dW1 = (const float*)d_in[10];
    const float* db1 = (const float*)d_in[11];
    const float* dW2 = (const float*)d_in[12];
    const float* db2 = (const float*)d_in[13];
    float* out = (float*)d_out;

    float *S, *SNEW, *C, *CNEW, *RES, *SM0;
    __nv_bfloat16 *Hhi, *Hlo, *HChi, *HClo, *Shi, *Slo, *Chi, *Clo, *WThi, *WTlo;
    cudaGetSymbolAddress((void**)&S, g_S);
    cudaGetSymbolAddress((void**)&SNEW, g_SNEW);
    cudaGetSymbolAddress((void**)&C, g_C);
    cudaGetSymbolAddress((void**)&CNEW, g_CNEW);
    cudaGetSymbolAddress((void**)&RES, g_RES);
    cudaGetSymbolAddress((void**)&SM0, g_SM0);
    cudaGetSymbolAddress((void**)&Hhi, g_Hhi);
    cudaGetSymbolAddress((void**)&Hlo, g_Hlo);
    cudaGetSymbolAddress((void**)&HChi, g_HChi);
    cudaGetSymbolAddress((void**)&HClo, g_HClo);
    cudaGetSymbolAddress((void**)&Shi, g_Shi);
    cudaGetSymbolAddress((void**)&Slo, g_Slo);
    cudaGetSymbolAddress((void**)&Chi, g_Chi);
    cudaGetSymbolAddress((void**)&Clo, g_Clo);
    cudaGetSymbolAddress((void**)&WThi, g_WThi);
    cudaGetSymbolAddress((void**)&WTlo, g_WTlo);

    cudaFuncSetAttribute((const void*)hmma_gemm<0, false>, cudaFuncAttributeMaxDynamicSharedMemorySize, GEMM_SMEM);
    cudaFuncSetAttribute((const void*)hmma_gemm<1, false>, cudaFuncAttributeMaxDynamicSharedMemorySize, GEMM_SMEM);
    cudaFuncSetAttribute((const void*)hmma_gemm<2, false>, cudaFuncAttributeMaxDynamicSharedMemorySize, GEMM_SMEM);
    cudaFuncSetAttribute((const void*)hmma_gemm<3, false>, cudaFuncAttributeMaxDynamicSharedMemorySize, GEMM_SMEM);
    cudaFuncSetAttribute((const void*)hmma_gemm<3, true>, cudaFuncAttributeMaxDynamicSharedMemorySize, GEMM_SMEM);

    // prep
    smlp0<<<Tdim, Ddim>>>(anchor, sW1, sb1, sW2, sb2, SM0); // bank-0 weights, fp32 inputs
    wtrans_banked<<<dim3(8, 8, 4 * NBdim), dim3(32, 8)>>>(sW1, sW2, cW1, cW2, WThi, WTlo);
    wtrans_single<<<dim3(8, 16), dim3(32, 8)>>>(dW1, Ddim, Hdim, WThi + WOFF_DW1, WTlo + WOFF_DW1);
    wtrans_single<<<dim3(16, 13), dim3(32, 8)>>>(dW2, Hdim, OUTdim, WThi + WOFF_DW2, WTlo + WOFF_DW2);
    init_c<<<(BAn * Ddim + 255) / 256, 256>>>(fe, C, Chi, Clo);

    const int BIG = 1 << 30;
    const dim3 grid1(2, ROWS / 128 + BAn / 128); // batched sG1 + cG1 (iters >= 1)
    const dim3 gridC(2, BAn / 128);              // c-GEMMs
    const dim3 gridS(2, ROWS / 128);             // sG2
    const dim3 gridD1(4, ROWS / 128);            // decoder1 N=512
    const dim3 gridD2a(3, ROWS / 128);           // decoder2 cols 0..383 (clean loop)
    const dim3 gridD2b(1, ROWS / 128);           // decoder2 cols 384..400 (TAIL)

    for (int i = 0; i < NBdim; i++) {
        const size_t wo = (size_t)i * Ddim * Ddim;
        const int bo = i * Ddim;
        if (i == 0) {
            // iter 0: s path collapses to 6 unique rows (S = broadcast anchor)
            hmma_gemm<0, false><<<gridC, 256, GEMM_SMEM>>>(
                Chi, Clo, Ddim, WThi + WOFF_CW1 + wo, WTlo + WOFF_CW1 + wo, cb1 + bo,
                Ddim, Ddim, nullptr, HChi, HClo, Hdim, nullptr, nullptr, nullptr,
                BIG, 0, nullptr, nullptr, 0, nullptr, nullptr, nullptr, nullptr, nullptr, 0);
            hmma_gemm<1, false><<<gridC, 256, GEMM_SMEM>>>(
                HChi, HClo, Hdim, WThi + WOFF_CW2 + wo, WTlo + WOFF_CW2 + wo, cb2 + bo,
                Ddim, Ddim, CNEW, nullptr, nullptr, Ddim, nullptr, nullptr, nullptr,
                BIG, 0, nullptr, nullptr, 0, nullptr, nullptr, nullptr, nullptr, nullptr, 0);
            iter0_all<<<(BAn * Ddim + 255) / 256, 256>>>(anchor, SM0, CNEW, S, Shi, Slo, C, Chi, Clo);
        } else {
            // batched: s_hidden (relu) -> Hhi/Hlo || c_hidden (relu) -> HChi/HClo
            hmma_gemm<0, false><<<grid1, 256, GEMM_SMEM>>>(
                Shi, Slo, Ddim, WThi + WOFF_SW1 + wo, WTlo + WOFF_SW1 + wo, sb1 + bo,
                Ddim, Ddim, nullptr, Hhi, Hlo, Hdim, nullptr, nullptr, nullptr,
                ROWS / 128, 0,
                Chi, Clo, Ddim, WThi + WOFF_CW1 + wo, WTlo + WOFF_CW1 + wo, cb1 + bo,
                HChi, HClo, Hdim);
            hmma_gemm<1, false><<<gridC, 256, GEMM_SMEM>>>(
                HChi, HClo, Hdim, WThi + WOFF_CW2 + wo, WTlo + WOFF_CW2 + wo, cb2 + bo,
                Ddim, Ddim, CNEW, nullptr, nullptr, Ddim, nullptr, nullptr, nullptr,
                BIG, 0, nullptr, nullptr, 0, nullptr, nullptr, nullptr, nullptr, nullptr, 0);
            hmma_gemm<2, false><<<gridS, 256, GEMM_SMEM>>>(
                Hhi, Hlo, Hdim, WThi + WOFF_SW2 + wo, WTlo + WOFF_SW2 + wo, sb2 + bo,
                Ddim, Ddim, nullptr, Shi, Slo, Ddim, CNEW, SNEW, S,
                BIG, 0, nullptr, nullptr, 0, nullptr, nullptr, nullptr, nullptr, nullptr, 0);
            agg_update_c<<<(BAn * Ddim + 255) / 256, 256>>>(SNEW, C, Chi, Clo);
        }
    }

    // decoder
    hmma_gemm<0, false><<<gridD1, 256, GEMM_SMEM>>>(
        Shi, Slo, Ddim, WThi + WOFF_DW1, WTlo + WOFF_DW1, db1,
        Hdim, Ddim, nullptr, Hhi, Hlo, Hdim, nullptr, nullptr, nullptr,
        BIG, 0, nullptr, nullptr, 0, nullptr, nullptr, nullptr, nullptr, nullptr, 0);
    // decoder-2 main (cols 0..383, clean mainloop) + tail (cols 384..400)
    hmma_gemm<3, false><<<gridD2a, 256, GEMM_SMEM>>>(
        Hhi, Hlo, Hdim, WThi + WOFF_DW2, WTlo + WOFF_DW2, db2,
        OUTdim, Hdim, RES, nullptr, nullptr, OUTdim, nullptr, out, nullptr,
        BIG, 0, nullptr, nullptr, 0, nullptr, nullptr, nullptr, nullptr, nullptr, 0);
    hmma_gemm<3, true><<<gridD2b, 256, GEMM_SMEM>>>(
        Hhi, Hlo, Hdim, WThi + WOFF_DW2, WTlo + WOFF_DW2, db2,
        OUTdim, Hdim, RES, nullptr, nullptr, OUTdim, nullptr, out, nullptr,
        BIG, 3, nullptr, nullptr, 0, nullptr, nullptr, nullptr, nullptr, nullptr, 0);

    decode_cov<<<(unsigned)(((long)ROWS * 80 + 255) / 256), 256>>>(RES, out);
}